// round 5
// baseline (speedup 1.0000x reference)
#include <cuda_runtime.h>
#include <cstdint>
#include <math.h>

#define BATCH   2048
#define IN_DIM  512
#define NUM_OUT 256

#define BM 32
#define BN 64
#define BK 32
#define NTHREADS 128
#define NSTEPS (IN_DIM / BK)   // 16

typedef unsigned long long ull;

// Precomputed -sigmoid(5*W_raw), transposed to [k][o] and duplicated along o:
// g_wdup[k*512 + 2*o] == g_wdup[k*512 + 2*o + 1] == -sigmoid(5*W_raw[o][k])
__device__ float g_wdup[IN_DIM * NUM_OUT * 2];

// Coalesced: consecutive threads read consecutive k of one W row (float4),
// write 4 scattered float2 stores (fire-and-forget).
__global__ void precompute_kernel(const float* __restrict__ Wraw) {
    int i = blockIdx.x * blockDim.x + threadIdx.x;   // 0 .. 32767
    if (i < NUM_OUT * (IN_DIM / 4)) {
        int o  = i >> 7;          // 0..255
        int k4 = (i & 127) * 4;   // 0,4,...,508
        float4 v = *reinterpret_cast<const float4*>(&Wraw[o * IN_DIM + k4]);
        float w0 = 1.0f / (1.0f + __expf(-5.0f * v.x));
        float w1 = 1.0f / (1.0f + __expf(-5.0f * v.y));
        float w2 = 1.0f / (1.0f + __expf(-5.0f * v.z));
        float w3 = 1.0f / (1.0f + __expf(-5.0f * v.w));
        float2 p;
        p.x = -w0; p.y = -w0;
        *reinterpret_cast<float2*>(&g_wdup[(k4 + 0) * (2 * NUM_OUT) + 2 * o]) = p;
        p.x = -w1; p.y = -w1;
        *reinterpret_cast<float2*>(&g_wdup[(k4 + 1) * (2 * NUM_OUT) + 2 * o]) = p;
        p.x = -w2; p.y = -w2;
        *reinterpret_cast<float2*>(&g_wdup[(k4 + 2) * (2 * NUM_OUT) + 2 * o]) = p;
        p.x = -w3; p.y = -w3;
        *reinterpret_cast<float2*>(&g_wdup[(k4 + 3) * (2 * NUM_OUT) + 2 * o]) = p;
    }
}

__device__ __forceinline__ ull ffma2(ull a, ull b, ull c) {
    ull d;
    asm("fma.rn.f32x2 %0, %1, %2, %3;" : "=l"(d) : "l"(a), "l"(b), "l"(c));
    return d;
}
__device__ __forceinline__ ull fmul2(ull a, ull b) {
    ull d;
    asm("mul.rn.f32x2 %0, %1, %2;" : "=l"(d) : "l"(a), "l"(b));
    return d;
}
__device__ __forceinline__ void cp_async16(uint32_t smem, const void* gptr) {
    asm volatile("cp.async.cg.shared.global [%0], [%1], 16;" :: "r"(smem), "l"(gptr));
}

// 32(M) x 64(N) tile per CTA, full K=512, no split, no combine.
// Thread tile 4 rows x 4 cols; accumulator packs two M-rows per f32x2 reg.
// z = 1 + (-w) * (1 - x) = fma(nw, t, 1).
__global__ void __launch_bounds__(NTHREADS, 2)
logic_kernel(const float* __restrict__ x, float* __restrict__ out) {
    // xs rows padded to 36 floats (144B, 16B-aligned row stride)
    __shared__ __align__(16) float xs[2][BK][36];
    // ws: duplicated -w tile: row k holds 128 floats = 64 cols duplicated (512B)
    __shared__ __align__(16) float ws[2][BK][2 * BN];

    const int tid = threadIdx.x;
    const int bm0 = blockIdx.x * BM;
    const int bn  = blockIdx.y;

    const int tc = tid & 15;   // 16 col-groups of 4 outputs
    const int tr = tid >> 4;   // 8 row-groups of 4 rows

    // x staging: row xm (0..31), k-quarter xq (8 k's each)
    const int xm = tid & 31;
    const int xq = tid >> 5;   // 0..3

    const ull ONE2 = 0x3F8000003F800000ULL;   // (1.0f, 1.0f)
    ull acc[2][4];
#pragma unroll
    for (int i = 0; i < 2; ++i)
#pragma unroll
        for (int j = 0; j < 4; ++j) acc[i][j] = ONE2;

    const float* xrow = x + (ull)(bm0 + xm) * IN_DIM + xq * 8;

    // ---------------- prologue: fill buffer 0 ----------------
    {
        float4 a = *reinterpret_cast<const float4*>(xrow + 0);
        float4 b = *reinterpret_cast<const float4*>(xrow + 4);
        // w tile stage 0: 32 rows x 512B = 1024 x 16B chunks, 8 per thread
#pragma unroll
        for (int c = 0; c < 8; ++c) {
            int idx = c * 128 + tid;
            int k   = idx >> 5;        // 0..31
            int col = idx & 31;        // 16B chunk within row
            const float* src = g_wdup + (ull)k * (2 * NUM_OUT) + bn * (2 * BN) + col * 4;
            cp_async16((uint32_t)__cvta_generic_to_shared(&ws[0][k][col * 4]), src);
        }
        asm volatile("cp.async.commit_group;" ::: "memory");
        int kb = xq * 8;
        xs[0][kb + 0][xm] = 1.0f - a.x;
        xs[0][kb + 1][xm] = 1.0f - a.y;
        xs[0][kb + 2][xm] = 1.0f - a.z;
        xs[0][kb + 3][xm] = 1.0f - a.w;
        xs[0][kb + 4][xm] = 1.0f - b.x;
        xs[0][kb + 5][xm] = 1.0f - b.y;
        xs[0][kb + 6][xm] = 1.0f - b.z;
        xs[0][kb + 7][xm] = 1.0f - b.w;
    }

    // ---------------- main loop ----------------
    for (int step = 0; step < NSTEPS; ++step) {
        const int buf  = step & 1;
        const int nbuf = buf ^ 1;
        const bool more = (step + 1 < NSTEPS);

        __syncthreads();   // compute(step-1) done; x STS(step) visible

        float4 a, b;
        if (more) {
            const float* xp = xrow + (step + 1) * BK;
            a = *reinterpret_cast<const float4*>(xp + 0);
            b = *reinterpret_cast<const float4*>(xp + 4);
            int k0 = (step + 1) * BK;
#pragma unroll
            for (int c = 0; c < 8; ++c) {
                int idx = c * 128 + tid;
                int k   = idx >> 5;
                int col = idx & 31;
                const float* src = g_wdup + (ull)(k0 + k) * (2 * NUM_OUT) + bn * (2 * BN) + col * 4;
                cp_async16((uint32_t)__cvta_generic_to_shared(&ws[nbuf][k][col * 4]), src);
            }
        }
        asm volatile("cp.async.commit_group;" ::: "memory");
        asm volatile("cp.async.wait_group 1;" ::: "memory");
        __syncthreads();   // ws[buf] fully landed

        // ---------- compute on buf ----------
#pragma unroll
        for (int k = 0; k < BK; ++k) {
            ulonglong2 xp = *reinterpret_cast<const ulonglong2*>(&xs[buf][k][tr * 4]);
            ulonglong2 wa = *reinterpret_cast<const ulonglong2*>(&ws[buf][k][tc * 8]);
            ulonglong2 wb = *reinterpret_cast<const ulonglong2*>(&ws[buf][k][tc * 8 + 4]);
            ull xv[2] = {xp.x, xp.y};               // row-pairs (tr*4+0,1), (tr*4+2,3)
            ull wv[4] = {wa.x, wa.y, wb.x, wb.y};   // (-w_j, -w_j) duplicated pairs
#pragma unroll
            for (int j = 0; j < 4; ++j) {
#pragma unroll
                for (int i = 0; i < 2; ++i) {
                    ull z = ffma2(wv[j], xv[i], ONE2);   // (1 - w*t, 1 - w*t)
                    acc[i][j] = fmul2(acc[i][j], z);
                }
            }
        }

        if (more) {
            int kb = xq * 8;
            xs[nbuf][kb + 0][xm] = 1.0f - a.x;
            xs[nbuf][kb + 1][xm] = 1.0f - a.y;
            xs[nbuf][kb + 2][xm] = 1.0f - a.z;
            xs[nbuf][kb + 3][xm] = 1.0f - a.w;
            xs[nbuf][kb + 4][xm] = 1.0f - b.x;
            xs[nbuf][kb + 5][xm] = 1.0f - b.y;
            xs[nbuf][kb + 6][xm] = 1.0f - b.z;
            xs[nbuf][kb + 7][xm] = 1.0f - b.w;
        }
    }

    // ---------------- epilogue: write final products ----------------
    float* orow = out + (ull)(bm0 + tr * 4) * NUM_OUT + bn * BN + tc * 4;
#pragma unroll
    for (int r = 0; r < 4; ++r) {
        int i = r >> 1;
        int h = r & 1;
        float4 v;
        v.x = __uint_as_float((unsigned)(acc[i][0] >> (h * 32)));
        v.y = __uint_as_float((unsigned)(acc[i][1] >> (h * 32)));
        v.z = __uint_as_float((unsigned)(acc[i][2] >> (h * 32)));
        v.w = __uint_as_float((unsigned)(acc[i][3] >> (h * 32)));
        *reinterpret_cast<float4*>(orow + (ull)r * NUM_OUT) = v;
    }
}

extern "C" void kernel_launch(void* const* d_in, const int* in_sizes, int n_in,
                              void* d_out, int out_size) {
    const float* x    = (const float*)d_in[0];   // [2048, 512]
    const float* Wraw = (const float*)d_in[1];   // [256, 512]
    float* out        = (float*)d_out;           // [2048, 256]

    precompute_kernel<<<(NUM_OUT * (IN_DIM / 4) + 127) / 128, 128>>>(Wraw);

    dim3 grid(BATCH / BM, NUM_OUT / BN);         // 64 x 4 = 256 CTAs
    logic_kernel<<<grid, NTHREADS>>>(x, out);
}

// round 6
// speedup vs baseline: 1.5247x; 1.5247x over previous
#include <cuda_runtime.h>
#include <cstdint>
#include <math.h>

#define BATCH   2048
#define IN_DIM  512
#define NUM_OUT 256

#define BM 64
#define BN 128
#define BK 16
#define NTHREADS 128
#define KSPLIT 4
#define KCHUNK (IN_DIM / KSPLIT)    // 128
#define NSTEPS (KCHUNK / BK)        // 8

typedef unsigned long long ull;

// g_w[k][o] = -sigmoid(5 * W_raw[o][k]); [512][256] floats, 512 KB.
__device__ float g_w[IN_DIM * NUM_OUT];
// Partial products per K-chunk: 8 MB
__device__ float g_part[KSPLIT][BATCH * NUM_OUT];

// Coalesced transpose precompute: load W[o][k] coalesced along k,
// store g_w[k][o] coalesced along o, sigmoid applied on the way out.
__global__ void precompute_kernel(const float* __restrict__ Wraw) {
    __shared__ float t[32][33];
    const int o0 = blockIdx.x * 32;
    const int k0 = blockIdx.y * 32;
    const int tx = threadIdx.x;      // 0..31
    const int ty = threadIdx.y;      // 0..7
#pragma unroll
    for (int j = 0; j < 32; j += 8)
        t[ty + j][tx] = Wraw[(o0 + ty + j) * IN_DIM + k0 + tx];
    __syncthreads();
#pragma unroll
    for (int j = 0; j < 32; j += 8) {
        float v = t[tx][ty + j];     // = W[o0+tx][k0+ty+j]
        float w = 1.0f / (1.0f + __expf(-5.0f * v));
        g_w[(k0 + ty + j) * NUM_OUT + o0 + tx] = -w;
    }
}

__device__ __forceinline__ ull ffma2(ull a, ull b, ull c) {
    ull d;
    asm("fma.rn.f32x2 %0, %1, %2, %3;" : "=l"(d) : "l"(a), "l"(b), "l"(c));
    return d;
}
__device__ __forceinline__ ull fmul2(ull a, ull b) {
    ull d;
    asm("mul.rn.f32x2 %0, %1, %2;" : "=l"(d) : "l"(a), "l"(b));
    return d;
}
__device__ __forceinline__ void cp_async16(uint32_t smem, const void* gptr) {
    asm volatile("cp.async.cg.shared.global [%0], [%1], 16;" :: "r"(smem), "l"(gptr));
}

// 64(M) x 128(N) tile per CTA over one 128-K chunk. Thread tile 8x8.
// Accumulator packs two adjacent N-cols per f32x2: no w duplication needed.
// x is stored duplicated in smem: xs[k][2*row] = xs[k][2*row+1] = 1-x.
// w row stored piece-permuted: 16B piece p (p=0..31, logical floats 4p..4p+3)
// lives at phys chunk (p even -> p/2, p odd -> 16 + p/2), so each thread's two
// LDS.128 (pieces 2c and 2c+1) hit contiguous 256B regions -> conflict-free.
__global__ void __launch_bounds__(NTHREADS, 2)
logic_kernel(const float* __restrict__ x) {
    __shared__ __align__(16) float xs[2][BK][2 * BM + 4];   // 132 floats/row
    __shared__ __align__(16) float ws[2][BK][BN + 4];       // 132 floats/row

    const int tid = threadIdx.x;
    const int bm0 = blockIdx.x * BM;
    const int bn  = blockIdx.y;          // 0..1
    const int kz  = blockIdx.z;          // K-chunk
    const int kbase = kz * KCHUNK;

    const int cg = tid & 15;   // col-group: 8 cols each
    const int rg = tid >> 4;   // row-group: 8 rows each

    // x staging: row xm (0..63), k-half xq (8 k's each)
    const int xm = tid & 63;
    const int xq = tid >> 6;   // 0 or 1

    const ull ONE2 = 0x3F8000003F800000ULL;
    ull acc[8][4];
#pragma unroll
    for (int i = 0; i < 8; ++i)
#pragma unroll
        for (int j = 0; j < 4; ++j) acc[i][j] = ONE2;

    const float* xrow = x + (ull)(bm0 + xm) * IN_DIM + kbase + xq * 8;

    // w fill: 16 rows x 32 chunks of 16B = 512 chunks, 4 per thread.
    // chunk q: gmem float offset = (q&15)*8 + (q>>4)*4  (piece permutation)
    // ---------------- prologue: fill buffer 0 ----------------
    {
        float4 a = *reinterpret_cast<const float4*>(xrow + 0);
        float4 b = *reinterpret_cast<const float4*>(xrow + 4);
#pragma unroll
        for (int c = 0; c < 4; ++c) {
            int idx = c * 128 + tid;
            int k   = idx >> 5;        // 0..15
            int q   = idx & 31;        // chunk within row
            int goff = ((q & 15) * 8 + (q >> 4) * 4);
            const float* src = g_w + (ull)(kbase + k) * NUM_OUT + bn * BN + goff;
            cp_async16((uint32_t)__cvta_generic_to_shared(&ws[0][k][q * 4]), src);
        }
        asm volatile("cp.async.commit_group;" ::: "memory");
        int kb = xq * 8;
        float2 p;
#define XDUP(slot, val) p.x = 1.0f - (val); p.y = p.x; \
        *reinterpret_cast<float2*>(&xs[0][kb + slot][2 * xm]) = p;
        XDUP(0, a.x) XDUP(1, a.y) XDUP(2, a.z) XDUP(3, a.w)
        XDUP(4, b.x) XDUP(5, b.y) XDUP(6, b.z) XDUP(7, b.w)
#undef XDUP
    }

    // ---------------- main loop ----------------
    for (int step = 0; step < NSTEPS; ++step) {
        const int buf  = step & 1;
        const int nbuf = buf ^ 1;
        const bool more = (step + 1 < NSTEPS);

        __syncthreads();   // compute(step-1) done; x STS(step) visible

        float4 a, b;
        if (more) {
            const float* xp = xrow + (step + 1) * BK;
            a = *reinterpret_cast<const float4*>(xp + 0);
            b = *reinterpret_cast<const float4*>(xp + 4);
            int k0 = kbase + (step + 1) * BK;
#pragma unroll
            for (int c = 0; c < 4; ++c) {
                int idx = c * 128 + tid;
                int k   = idx >> 5;
                int q   = idx & 31;
                int goff = ((q & 15) * 8 + (q >> 4) * 4);
                const float* src = g_w + (ull)(k0 + k) * NUM_OUT + bn * BN + goff;
                cp_async16((uint32_t)__cvta_generic_to_shared(&ws[nbuf][k][q * 4]), src);
            }
        }
        asm volatile("cp.async.commit_group;" ::: "memory");
        asm volatile("cp.async.wait_group 1;" ::: "memory");
        __syncthreads();   // ws[buf] fully landed

        // ---------- compute on buf ----------
#pragma unroll
        for (int k = 0; k < BK; ++k) {
            // x: 8 duplicated pairs for rows rg*8 .. rg*8+7 (contiguous 64B)
            ulonglong2 xa = *reinterpret_cast<const ulonglong2*>(&xs[buf][k][rg * 16]);
            ulonglong2 xb = *reinterpret_cast<const ulonglong2*>(&xs[buf][k][rg * 16 + 4]);
            ulonglong2 xc = *reinterpret_cast<const ulonglong2*>(&xs[buf][k][rg * 16 + 8]);
            ulonglong2 xd = *reinterpret_cast<const ulonglong2*>(&xs[buf][k][rg * 16 + 12]);
            // w: cols cg*8..cg*8+7 -> phys chunks cg (floats 0..3) and 16+cg (4..7)
            ulonglong2 wa = *reinterpret_cast<const ulonglong2*>(&ws[buf][k][cg * 4]);
            ulonglong2 wb = *reinterpret_cast<const ulonglong2*>(&ws[buf][k][64 + cg * 4]);
            ull xv[8] = {xa.x, xa.y, xb.x, xb.y, xc.x, xc.y, xd.x, xd.y};
            ull wv[4] = {wa.x, wa.y, wb.x, wb.y};   // (w0,w1)(w2,w3)(w4,w5)(w6,w7)
#pragma unroll
            for (int i = 0; i < 8; ++i) {
#pragma unroll
                for (int j = 0; j < 4; ++j) {
                    ull z = ffma2(wv[j], xv[i], ONE2);   // (1-w*t, 1-w*t)
                    acc[i][j] = fmul2(acc[i][j], z);
                }
            }
        }

        if (more) {
            int kb = xq * 8;
            float2 p;
#define XDUP(slot, val) p.x = 1.0f - (val); p.y = p.x; \
            *reinterpret_cast<float2*>(&xs[nbuf][kb + slot][2 * xm]) = p;
            XDUP(0, a.x) XDUP(1, a.y) XDUP(2, a.z) XDUP(3, a.w)
            XDUP(4, b.x) XDUP(5, b.y) XDUP(6, b.z) XDUP(7, b.w)
#undef XDUP
        }
    }

    // ---------------- epilogue: write partial products ----------------
    float* orow = g_part[kz] + (ull)(bm0 + rg * 8) * NUM_OUT + bn * BN + cg * 8;
#pragma unroll
    for (int i = 0; i < 8; ++i) {
        float4 v0, v1;
        v0.x = __uint_as_float((unsigned)(acc[i][0]));
        v0.y = __uint_as_float((unsigned)(acc[i][0] >> 32));
        v0.z = __uint_as_float((unsigned)(acc[i][1]));
        v0.w = __uint_as_float((unsigned)(acc[i][1] >> 32));
        v1.x = __uint_as_float((unsigned)(acc[i][2]));
        v1.y = __uint_as_float((unsigned)(acc[i][2] >> 32));
        v1.z = __uint_as_float((unsigned)(acc[i][3]));
        v1.w = __uint_as_float((unsigned)(acc[i][3] >> 32));
        *reinterpret_cast<float4*>(orow + (ull)i * NUM_OUT)     = v0;
        *reinterpret_cast<float4*>(orow + (ull)i * NUM_OUT + 4) = v1;
    }
}

// out = p0 * p1 * p2 * p3 elementwise (float4-vectorized)
__global__ void combine_kernel(float* __restrict__ out) {
    int i = blockIdx.x * blockDim.x + threadIdx.x;
    if (i < (BATCH * NUM_OUT) / 4) {
        float4 a = reinterpret_cast<const float4*>(g_part[0])[i];
        float4 b = reinterpret_cast<const float4*>(g_part[1])[i];
        float4 c = reinterpret_cast<const float4*>(g_part[2])[i];
        float4 d = reinterpret_cast<const float4*>(g_part[3])[i];
        float4 v;
        v.x = (a.x * b.x) * (c.x * d.x);
        v.y = (a.y * b.y) * (c.y * d.y);
        v.z = (a.z * b.z) * (c.z * d.z);
        v.w = (a.w * b.w) * (c.w * d.w);
        reinterpret_cast<float4*>(out)[i] = v;
    }
}

extern "C" void kernel_launch(void* const* d_in, const int* in_sizes, int n_in,
                              void* d_out, int out_size) {
    const float* x    = (const float*)d_in[0];   // [2048, 512]
    const float* Wraw = (const float*)d_in[1];   // [256, 512]
    float* out        = (float*)d_out;           // [2048, 256]

    dim3 pgrid(NUM_OUT / 32, IN_DIM / 32);       // 8 x 16
    dim3 pblk(32, 8);
    precompute_kernel<<<pgrid, pblk>>>(Wraw);

    dim3 grid(BATCH / BM, NUM_OUT / BN, KSPLIT); // 32 x 2 x 4 = 256 CTAs
    logic_kernel<<<grid, NTHREADS>>>(x);

    combine_kernel<<<(BATCH * NUM_OUT / 4 + 255) / 256, 256>>>(out);
}